// round 14
// baseline (speedup 1.0000x reference)
#include <cuda_runtime.h>
#include <cuda_fp16.h>
#include <cstdint>

#define NSEQ   10400     // B*S = 32*325
#define LSTEPS 192       // L
#define HID    128       // D_MODEL
#define NH     8
#define SLEN   325
#define NB     32
#define SCALE  0.08838834764831845f  // 1/sqrt(128)

// ---------------- scratch (static device arrays; no allocation) ----------------
__device__ float g_xT[LSTEPS * NSEQ];                    //  8 MB  x transposed [l][n]
__device__ __align__(16) __half g_Wh16[16 * 512 * HID];  //  2 MB  swizzled fp16 W tiles
__device__ float g_bias2[16 * 512];                      //  bih+bhh by col n
__device__ float g_wih2[16 * 512];                       //  Wih by col n
__device__ float g_q[NH * NSEQ * HID];                   // 43 MB  q final hidden [h][n][d]
__device__ float g_kT[NH * HID * NSEQ];                  // 43 MB  k final hidden [h][d][n]
__device__ float g_v[NH * NSEQ * LSTEPS];                // 64 MB  v outputs [h][n][l]

__device__ __forceinline__ float sigf(float x) {
    return __fdividef(1.f, 1.f + __expf(-x));
}

// MUFU.TANH fast paths (1 MUFU each)
__device__ __forceinline__ float tanha(float x) {
    float y;
    asm("tanh.approx.f32 %0, %1;" : "=f"(y) : "f"(x));
    return y;
}
__device__ __forceinline__ float siga(float x) {
    return fmaf(0.5f, tanha(0.5f * x), 0.5f);
}

__device__ __forceinline__ void cpa16(void* dst_smem, const void* src) {
    unsigned s = (unsigned)__cvta_generic_to_shared(dst_smem);
    asm volatile("cp.async.cg.shared.global [%0], [%1], 16;" :: "r"(s), "l"(src));
}

__device__ __forceinline__ void ldsm4(uint32_t* r, uint32_t addr) {
    asm volatile("ldmatrix.sync.aligned.m8n8.x4.shared.b16 {%0,%1,%2,%3}, [%4];"
                 : "=r"(r[0]), "=r"(r[1]), "=r"(r[2]), "=r"(r[3]) : "r"(addr));
}

__device__ __forceinline__ void mma16816(float* c, const uint32_t* a, const uint32_t* b) {
    asm volatile(
        "mma.sync.aligned.m16n8k16.row.col.f32.f16.f16.f32 "
        "{%0,%1,%2,%3}, {%4,%5,%6,%7}, {%8,%9}, {%0,%1,%2,%3};"
        : "+f"(c[0]), "+f"(c[1]), "+f"(c[2]), "+f"(c[3])
        : "r"(a[0]), "r"(a[1]), "r"(a[2]), "r"(a[3]), "r"(b[0]), "r"(b[1]));
}

// ---------------- prep: transpose x to [l][n] ----------------
__global__ void k_prep_x(const float* __restrict__ x) {
    int i = blockIdx.x * 256 + threadIdx.x;
    if (i < LSTEPS * NSEQ) {
        int l = i / NSEQ, n = i % NSEQ;
        g_xT[i] = x[(size_t)n * LSTEPS + l];
    }
}

// ---------------- prep: fp16 weights in mma col layout, XOR-swizzled ----------------
// col n of unit j, gate g (PyTorch order i,f,g,o): n = (g>>1)*256 + 2j + (g&1).
// B tile per hq: [n=512][k=128] fp16, row = 256 B, byte off = n*256 + ((2k)^((n&7)<<4)).
__global__ void k_prep_w16(const float* __restrict__ qWih, const float* __restrict__ qWhh,
                           const float* __restrict__ qbih, const float* __restrict__ qbhh,
                           const float* __restrict__ kWih, const float* __restrict__ kWhh,
                           const float* __restrict__ kbih, const float* __restrict__ kbhh) {
    int idx = blockIdx.x * 256 + threadIdx.x;
    if (idx >= 16 * 512 * HID) return;
    int hq = idx >> 16;
    int n  = (idx >> 7) & 511;
    int k  = idx & 127;
    int j = (n & 255) >> 1;
    int g = ((n >> 8) << 1) | (n & 1);
    int row = g * HID + j;
    int h = hq & 7;
    const float* Whh = (hq < 8) ? (qWhh + (size_t)h * 512 * HID)
                                : (kWhh + (size_t)h * 512 * HID);
    float val = Whh[row * HID + k];
    int off = n * 256 + ((2 * k) ^ ((n & 7) << 4));
    *(__half*)((char*)g_Wh16 + (size_t)hq * 131072 + off) = __float2half(val);
    if (k == 0) {
        const float* Wih = (hq < 8) ? qWih + h * 512 : kWih + h * 512;
        const float* bi  = (hq < 8) ? qbih + h * 512 : kbih + h * 512;
        const float* bh  = (hq < 8) ? qbhh + h * 512 : kbhh + h * 512;
        g_wih2[hq * 512 + n]  = Wih[row];
        g_bias2[hq * 512 + n] = bi[row] + bh[row];
    }
}

// ---------------- v LSTM: hidden size 1, one thread per (head, seq) ----------------
__global__ void k_v_lstm(const float* __restrict__ wih, const float* __restrict__ whh,
                         const float* __restrict__ bih, const float* __restrict__ bhh) {
    int idx = blockIdx.x * 256 + threadIdx.x;
    if (idx >= NH * NSEQ) return;
    int h = idx / NSEQ, n = idx % NSEQ;
    float wi[4], wh[4], bb[4];
#pragma unroll
    for (int g = 0; g < 4; g++) {
        wi[g] = wih[h * 4 + g];
        wh[g] = whh[h * 4 + g];
        bb[g] = bih[h * 4 + g] + bhh[h * 4 + g];
    }
    float hv = 0.f, cv = 0.f;
    float* vp = g_v + (size_t)idx * LSTEPS;
    for (int t = 0; t < LSTEPS; t++) {
        float xv = g_xT[t * NSEQ + n];
        float zi = wi[0] * xv + wh[0] * hv + bb[0];
        float zf = wi[1] * xv + wh[1] * hv + bb[1];
        float zg = wi[2] * xv + wh[2] * hv + bb[2];
        float zo = wi[3] * xv + wh[3] * hv + bb[3];
        cv = sigf(zf) * cv + sigf(zi) * tanhf(zg);
        hv = sigf(zo) * tanhf(cv);
        vp[t] = hv;
    }
}

// ---------------- q/k LSTM via mma.sync (HMMA) ----------------
// CTA = (hq, 32-seq tile), 512 threads = 16 warps = 2 seq-bands x 8 col-groups
// (R11 topology: keeps 16-warp latency hiding). NEW: ug0's time-invariant B
// fragments live in registers (64 regs) -> B-LDSM traffic halves; ug1 via ldmatrix.
// A tile (h fp16) double-buffered; band-private named barrier per step. c fp32 regs.
#define SM_B    0          // 131072 B
#define SM_A    131072     // 16384 B  h fp16, 2 bufs x [32 rows x 256B]
#define SM_BIAS 147456     // 2048 B
#define SM_WIH  149504     // 2048 B
#define SM_TOT  151552

__global__ __launch_bounds__(512, 1) void k_qk_mma() {
    extern __shared__ char smem[];
    const int hq  = blockIdx.y;
    const int n0  = blockIdx.x * 32;
    const int tid = threadIdx.x;
    const int wid = tid >> 5, lane = tid & 31;
    const int sb  = wid >> 3;          // seq band (16 seqs)
    const int cg  = wid & 7;           // col group (16 units)
    const int s0  = sb * 16;

    uint32_t smB = (uint32_t)__cvta_generic_to_shared(smem);
    uint32_t smA = smB + SM_A;
    float* biassm = (float*)(smem + SM_BIAS);
    float* wihsm  = (float*)(smem + SM_WIH);

    // stage B / bias / wih
    {
        const char* wsrc = (const char*)g_Wh16 + (size_t)hq * 131072;
        for (int i = tid; i < 8192; i += 512) cpa16(smem + SM_B + i * 16, wsrc + i * 16);
        if (tid < 128)
            cpa16(smem + SM_BIAS + tid * 16, (const char*)(g_bias2 + hq * 512) + tid * 16);
        else if (tid < 256)
            cpa16(smem + SM_WIH + (tid - 128) * 16,
                  (const char*)(g_wih2 + hq * 512) + (tid - 128) * 16);
        asm volatile("cp.async.commit_group;");
    }
    for (int i = tid; i < 2048; i += 512) ((uint32_t*)(smem + SM_A))[i] = 0u;  // h0=0 buf0
    asm volatile("cp.async.wait_group 0;");
    __syncthreads();

    // preload bias/wih: units u[ug][nt] = cg*16 + ug*8 + nt*4 + (lane&3)
    float bi_r[2][2][4], wi_r[2][2][4];
#pragma unroll
    for (int ug = 0; ug < 2; ug++)
#pragma unroll
        for (int nt = 0; nt < 2; nt++) {
            int u = cg * 16 + ug * 8 + nt * 4 + (lane & 3);
            bi_r[ug][nt][0] = biassm[2 * u];
            bi_r[ug][nt][1] = biassm[2 * u + 1];
            bi_r[ug][nt][2] = biassm[256 + 2 * u];
            bi_r[ug][nt][3] = biassm[257 + 2 * u];
            wi_r[ug][nt][0] = wihsm[2 * u];
            wi_r[ug][nt][1] = wihsm[2 * u + 1];
            wi_r[ug][nt][2] = wihsm[256 + 2 * u];
            wi_r[ug][nt][3] = wihsm[257 + 2 * u];
        }

    float cst[2][4];
#pragma unroll
    for (int a = 0; a < 2; a++)
#pragma unroll
        for (int b = 0; b < 4; b++) cst[a][b] = 0.f;

    // ldmatrix lane geometry (identical to R11)
    const int arow = s0 + (lane & 7) + ((lane >> 3) & 1) * 8;
    const uint32_t a_rowoff = arow * 256;
    const uint32_t a_xr = (arow & 7) << 4;
    const uint32_t a_kd = (lane >> 4) * 16;

    const int dlB = (lane & 7) + (lane >> 4) * 8;
    const uint32_t b_kd = ((lane >> 3) & 1) * 16;
    const uint32_t b_xr = (dlB & 7) << 4;
    const uint32_t b_rowbase = smB + (cg * 32 + dlB) * 256;   // ug0 if-cols
    const uint32_t bb1 = b_rowbase + 4096;                    // ug1 if-cols

    // register-resident B fragments for ug=0 (time-invariant)
    uint32_t Breg[8][8];
#pragma unroll
    for (int ks = 0; ks < 8; ks++) {
        uint32_t ko = ((uint32_t)(ks * 32) + b_kd) ^ b_xr;
        ldsm4(Breg[ks] + 0, b_rowbase + ko);            // ug0 (zi,zf) n-tiles
        ldsm4(Breg[ks] + 4, b_rowbase + 65536 + ko);    // ug0 (zg,zo) n-tiles
    }

    const int rlo = s0 + (lane >> 2), rhi = rlo + 8;
    const float* xlo_p = g_xT + n0 + rlo;
    const float* xhi_p = g_xT + n0 + rhi;

    const int bar_id = sb + 1;   // band-private named barrier

    for (int t = 0; t < LSTEPS; t++) {
        const uint32_t rbuf = smA + ((t & 1) ? 8192u : 0u);
        const uint32_t wbuf = smA + ((t & 1) ? 0u : 8192u);

        // per-thread x loads (1 L1 line per step per CTA)
        const float xlo = xlo_p[t * NSEQ];
        const float xhi = xhi_p[t * NSEQ];

        uint32_t afr[8][4];
#pragma unroll
        for (int ks = 0; ks < 8; ks++)
            ldsm4(afr[ks], rbuf + a_rowoff + (((uint32_t)(ks * 32) + a_kd) ^ a_xr));

        const bool last = (t == LSTEPS - 1);

        // ---- ug = 0: B from registers ----
        {
            float acc[16];
#pragma unroll
            for (int i = 0; i < 16; i++) acc[i] = 0.f;
#pragma unroll
            for (int ks = 0; ks < 8; ks++) {
                mma16816(acc + 0,  afr[ks], Breg[ks] + 0);
                mma16816(acc + 4,  afr[ks], Breg[ks] + 2);
                mma16816(acc + 8,  afr[ks], Breg[ks] + 4);
                mma16816(acc + 12, afr[ks], Breg[ks] + 6);
            }
#pragma unroll
            for (int cell = 0; cell < 4; cell++) {
                int nt = cell >> 1, hi = cell & 1;
                float xv  = hi ? xhi : xlo;
                int   row = hi ? rhi : rlo;
                float zi = acc[cell * 2]     + bi_r[0][nt][0] + wi_r[0][nt][0] * xv;
                float zf = acc[cell * 2 + 1] + bi_r[0][nt][1] + wi_r[0][nt][1] * xv;
                float zg = acc[8 + cell * 2] + bi_r[0][nt][2] + wi_r[0][nt][2] * xv;
                float zo = acc[9 + cell * 2] + bi_r[0][nt][3] + wi_r[0][nt][3] * xv;
                float cp = cst[0][cell];
                float cn = siga(zf) * cp + siga(zi) * tanha(zg);
                float hn = siga(zo) * tanha(cn);
                cst[0][cell] = cn;
                int u = cg * 16 + nt * 4 + (lane & 3);
                if (!last) {
                    uint32_t addr = wbuf + row * 256 + (((uint32_t)(2 * u)) ^ ((row & 7) << 4));
                    __half hh = __float2half(hn);
                    asm volatile("st.shared.b16 [%0], %1;"
                                 :: "r"(addr), "h"(*(unsigned short*)&hh));
                } else {
                    int ng = n0 + row;
                    if (hq < 8) g_q[((size_t)hq * NSEQ + ng) * HID + u] = hn;
                    else        g_kT[((size_t)(hq - 8) * HID + u) * NSEQ + ng] = hn;
                }
            }
        }

        // ---- ug = 1: B via ldmatrix ----
        {
            float acc[16];
#pragma unroll
            for (int i = 0; i < 16; i++) acc[i] = 0.f;
#pragma unroll
            for (int ks = 0; ks < 8; ks++) {
                uint32_t b0[4], b1[4];
                uint32_t ko = ((uint32_t)(ks * 32) + b_kd) ^ b_xr;
                ldsm4(b0, bb1 + ko);            // (zi,zf) n-tiles
                ldsm4(b1, bb1 + 65536 + ko);    // (zg,zo) n-tiles
                mma16816(acc + 0,  afr[ks], b0 + 0);
                mma16816(acc + 4,  afr[ks], b0 + 2);
                mma16816(acc + 8,  afr[ks], b1 + 0);
                mma16816(acc + 12, afr[ks], b1 + 2);
            }
#pragma unroll
            for (int cell = 0; cell < 4; cell++) {
                int nt = cell >> 1, hi = cell & 1;
                float xv  = hi ? xhi : xlo;
                int   row = hi ? rhi : rlo;
                float zi = acc[cell * 2]     + bi_r[1][nt][0] + wi_r[1][nt][0] * xv;
                float zf = acc[cell * 2 + 1] + bi_r[1][nt][1] + wi_r[1][nt][1] * xv;
                float zg = acc[8 + cell * 2] + bi_r[1][nt][2] + wi_r[1][nt][2] * xv;
                float zo = acc[9 + cell * 2] + bi_r[1][nt][3] + wi_r[1][nt][3] * xv;
                float cp = cst[1][cell];
                float cn = siga(zf) * cp + siga(zi) * tanha(zg);
                float hn = siga(zo) * tanha(cn);
                cst[1][cell] = cn;
                int u = cg * 16 + 8 + nt * 4 + (lane & 3);
                if (!last) {
                    uint32_t addr = wbuf + row * 256 + (((uint32_t)(2 * u)) ^ ((row & 7) << 4));
                    __half hh = __float2half(hn);
                    asm volatile("st.shared.b16 [%0], %1;"
                                 :: "r"(addr), "h"(*(unsigned short*)&hh));
                } else {
                    int ng = n0 + row;
                    if (hq < 8) g_q[((size_t)hq * NSEQ + ng) * HID + u] = hn;
                    else        g_kT[((size_t)(hq - 8) * HID + u) * NSEQ + ng] = hn;
                }
            }
        }

        // band-private barrier: h(t+1) stores visible to the band's 8 warps
        asm volatile("bar.sync %0, 256;" :: "r"(bar_id) : "memory");
    }
}

// ---------------- fused attention: scores + leaky + mask + softmax + attn@v + leaky ----------------
__global__ void k_attn(const float* __restrict__ graph, float* __restrict__ out) {
    int h = blockIdx.z, b = blockIdx.y, s0 = blockIdx.x * 16;
    int tid = threadIdx.x;
    __shared__ float qs[16][HID];
    __shared__ float sc[16][328];

    for (int i = tid; i < 16 * HID; i += 256) {
        int sq = i >> 7, d = i & 127;
        int s = s0 + sq;
        qs[sq][d] = (s < SLEN) ? g_q[((size_t)h * NSEQ + b * SLEN + s) * HID + d] : 0.f;
    }
    __syncthreads();

    for (int t = tid; t < SLEN; t += 256) {
        float acc[16];
#pragma unroll
        for (int i = 0; i < 16; i++) acc[i] = 0.f;
        const float* kp = g_kT + (size_t)h * HID * NSEQ + b * SLEN + t;
        for (int d = 0; d < HID; d += 4) {
            float k0 = kp[(size_t)d * NSEQ];
            float k1 = kp[(size_t)(d + 1) * NSEQ];
            float k2 = kp[(size_t)(d + 2) * NSEQ];
            float k3 = kp[(size_t)(d + 3) * NSEQ];
#pragma unroll
            for (int sq = 0; sq < 16; sq++) {
                float4 q4 = *reinterpret_cast<const float4*>(&qs[sq][d]);
                acc[sq] += k0 * q4.x + k1 * q4.y + k2 * q4.z + k3 * q4.w;
            }
        }
#pragma unroll
        for (int sq = 0; sq < 16; sq++) {
            int s = s0 + sq;
            float v = acc[sq] * SCALE;
            v = v >= 0.f ? v : 0.2f * v;
            bool keep = (s < SLEN) && ((s == t) || (graph[t * SLEN + s] != 0.f));
            sc[sq][t] = keep ? v : -1e9f;
        }
    }
    __syncthreads();

    {
        int r = tid >> 4, ln = tid & 15;
        float mx = -3.4e38f;
        for (int i = ln; i < SLEN; i += 16) mx = fmaxf(mx, sc[r][i]);
#pragma unroll
        for (int o = 1; o < 16; o <<= 1) mx = fmaxf(mx, __shfl_xor_sync(0xffffffffu, mx, o));
        float sum = 0.f;
        for (int i = ln; i < SLEN; i += 16) {
            float e = __expf(sc[r][i] - mx);
            sc[r][i] = e;
            sum += e;
        }
#pragma unroll
        for (int o = 1; o < 16; o <<= 1) sum += __shfl_xor_sync(0xffffffffu, sum, o);
        float inv = 1.f / sum;
        for (int i = ln; i < SLEN; i += 16) sc[r][i] *= inv;
    }
    __syncthreads();

    {
        int lg = tid & 63, sg = tid >> 6;
        float a2[4][3];
#pragma unroll
        for (int ss = 0; ss < 4; ss++) { a2[ss][0] = 0.f; a2[ss][1] = 0.f; a2[ss][2] = 0.f; }
        const float* vb = g_v + ((size_t)h * NSEQ + b * SLEN) * LSTEPS;
        for (int t = 0; t < SLEN; t++) {
            float a[4];
#pragma unroll
            for (int ss = 0; ss < 4; ss++) a[ss] = sc[sg * 4 + ss][t];
            const float* vr = vb + (size_t)t * LSTEPS + lg * 3;
            float v0 = vr[0], v1 = vr[1], v2 = vr[2];
#pragma unroll
            for (int ss = 0; ss < 4; ss++) {
                a2[ss][0] += a[ss] * v0;
                a2[ss][1] += a[ss] * v1;
                a2[ss][2] += a[ss] * v2;
            }
        }
#pragma unroll
        for (int ss = 0; ss < 4; ss++) {
            int s = s0 + sg * 4 + ss;
            if (s < SLEN) {
#pragma unroll
                for (int q = 0; q < 3; q++) {
                    float vv = a2[ss][q];
                    vv = vv >= 0.f ? vv : 0.2f * vv;
                    int l = lg * 3 + q;
                    out[(((size_t)(b * SLEN + s)) * LSTEPS + l) * NH + h] = vv;
                }
            }
        }
    }
}

// ---------------- launch ----------------
extern "C" void kernel_launch(void* const* d_in, const int* in_sizes, int n_in,
                              void* d_out, int out_size) {
    const float* x     = (const float*)d_in[0];
    const float* graph = (const float*)d_in[1];
    const float* qWih  = (const float*)d_in[2];
    const float* qWhh  = (const float*)d_in[3];
    const float* qbih  = (const float*)d_in[4];
    const float* qbhh  = (const float*)d_in[5];
    const float* kWih  = (const float*)d_in[6];
    const float* kWhh  = (const float*)d_in[7];
    const float* kbih  = (const float*)d_in[8];
    const float* kbhh  = (const float*)d_in[9];
    const float* vWih  = (const float*)d_in[10];
    const float* vWhh  = (const float*)d_in[11];
    const float* vbih  = (const float*)d_in[12];
    const float* vbhh  = (const float*)d_in[13];
    float* out = (float*)d_out;

    cudaFuncSetAttribute(k_qk_mma, cudaFuncAttributeMaxDynamicSharedMemorySize, SM_TOT);

    k_prep_x<<<(LSTEPS * NSEQ + 255) / 256, 256>>>(x);
    k_prep_w16<<<(16 * 512 * HID + 255) / 256, 256>>>(qWih, qWhh, qbih, qbhh,
                                                      kWih, kWhh, kbih, kbhh);
    k_v_lstm<<<(NH * NSEQ + 255) / 256, 256>>>(vWih, vWhh, vbih, vbhh);
    k_qk_mma<<<dim3(325, 16, 1), 512, SM_TOT>>>();
    k_attn<<<dim3(21, NB, NH), 256>>>(graph, out);
}

// round 16
// speedup vs baseline: 1.3817x; 1.3817x over previous
#include <cuda_runtime.h>
#include <cuda_fp16.h>
#include <cstdint>

#define NSEQ   10400     // B*S = 32*325
#define LSTEPS 192       // L
#define HID    128       // D_MODEL
#define NH     8
#define SLEN   325
#define NB     32
#define SCALE  0.08838834764831845f  // 1/sqrt(128)

// ---------------- scratch (static device arrays; no allocation) ----------------
__device__ float g_xT[LSTEPS * NSEQ];                    //  8 MB  x transposed [l][n]
__device__ __align__(16) __half g_Wh16[16 * 512 * HID];  //  2 MB  swizzled fp16 W tiles
__device__ float g_bias2[16 * 512];                      //  bih+bhh by col n
__device__ float g_wih2[16 * 512];                       //  Wih by col n
__device__ float g_q[NH * NSEQ * HID];                   // 43 MB  q final hidden [h][n][d]
__device__ float g_kT[NH * HID * NSEQ];                  // 43 MB  k final hidden [h][d][n]
__device__ float g_v[NH * NSEQ * LSTEPS];                // 64 MB  v outputs [h][n][l]

__device__ __forceinline__ float sigf(float x) {
    return __fdividef(1.f, 1.f + __expf(-x));
}

// MUFU.TANH fast paths (1 MUFU each)
__device__ __forceinline__ float tanha(float x) {
    float y;
    asm("tanh.approx.f32 %0, %1;" : "=f"(y) : "f"(x));
    return y;
}
__device__ __forceinline__ float siga(float x) {
    return fmaf(0.5f, tanha(0.5f * x), 0.5f);
}

__device__ __forceinline__ void cpa16(void* dst_smem, const void* src) {
    unsigned s = (unsigned)__cvta_generic_to_shared(dst_smem);
    asm volatile("cp.async.cg.shared.global [%0], [%1], 16;" :: "r"(s), "l"(src));
}

__device__ __forceinline__ void ldsm4(uint32_t* r, uint32_t addr) {
    asm volatile("ldmatrix.sync.aligned.m8n8.x4.shared.b16 {%0,%1,%2,%3}, [%4];"
                 : "=r"(r[0]), "=r"(r[1]), "=r"(r[2]), "=r"(r[3]) : "r"(addr));
}

__device__ __forceinline__ void mma16816(float* c, const uint32_t* a, const uint32_t* b) {
    asm volatile(
        "mma.sync.aligned.m16n8k16.row.col.f32.f16.f16.f32 "
        "{%0,%1,%2,%3}, {%4,%5,%6,%7}, {%8,%9}, {%0,%1,%2,%3};"
        : "+f"(c[0]), "+f"(c[1]), "+f"(c[2]), "+f"(c[3])
        : "r"(a[0]), "r"(a[1]), "r"(a[2]), "r"(a[3]), "r"(b[0]), "r"(b[1]));
}

// ---------------- prep: transpose x to [l][n] ----------------
__global__ void k_prep_x(const float* __restrict__ x) {
    int i = blockIdx.x * 256 + threadIdx.x;
    if (i < LSTEPS * NSEQ) {
        int l = i / NSEQ, n = i % NSEQ;
        g_xT[i] = x[(size_t)n * LSTEPS + l];
    }
}

// ---------------- prep: fp16 weights in mma col layout, XOR-swizzled ----------------
// col n of unit j, gate g (PyTorch order i,f,g,o): n = (g>>1)*256 + 2j + (g&1).
// B tile per hq: [n=512][k=128] fp16, row = 256 B, byte off = n*256 + ((2k)^((n&7)<<4)).
__global__ void k_prep_w16(const float* __restrict__ qWih, const float* __restrict__ qWhh,
                           const float* __restrict__ qbih, const float* __restrict__ qbhh,
                           const float* __restrict__ kWih, const float* __restrict__ kWhh,
                           const float* __restrict__ kbih, const float* __restrict__ kbhh) {
    int idx = blockIdx.x * 256 + threadIdx.x;
    if (idx >= 16 * 512 * HID) return;
    int hq = idx >> 16;
    int n  = (idx >> 7) & 511;
    int k  = idx & 127;
    int j = (n & 255) >> 1;
    int g = ((n >> 8) << 1) | (n & 1);
    int row = g * HID + j;
    int h = hq & 7;
    const float* Whh = (hq < 8) ? (qWhh + (size_t)h * 512 * HID)
                                : (kWhh + (size_t)h * 512 * HID);
    float val = Whh[row * HID + k];
    int off = n * 256 + ((2 * k) ^ ((n & 7) << 4));
    *(__half*)((char*)g_Wh16 + (size_t)hq * 131072 + off) = __float2half(val);
    if (k == 0) {
        const float* Wih = (hq < 8) ? qWih + h * 512 : kWih + h * 512;
        const float* bi  = (hq < 8) ? qbih + h * 512 : kbih + h * 512;
        const float* bh  = (hq < 8) ? qbhh + h * 512 : kbhh + h * 512;
        g_wih2[hq * 512 + n]  = Wih[row];
        g_bias2[hq * 512 + n] = bi[row] + bh[row];
    }
}

// ---------------- v LSTM: hidden size 1, one thread per (head, seq) ----------------
__global__ void k_v_lstm(const float* __restrict__ wih, const float* __restrict__ whh,
                         const float* __restrict__ bih, const float* __restrict__ bhh) {
    int idx = blockIdx.x * 256 + threadIdx.x;
    if (idx >= NH * NSEQ) return;
    int h = idx / NSEQ, n = idx % NSEQ;
    float wi[4], wh[4], bb[4];
#pragma unroll
    for (int g = 0; g < 4; g++) {
        wi[g] = wih[h * 4 + g];
        wh[g] = whh[h * 4 + g];
        bb[g] = bih[h * 4 + g] + bhh[h * 4 + g];
    }
    float hv = 0.f, cv = 0.f;
    float* vp = g_v + (size_t)idx * LSTEPS;
    for (int t = 0; t < LSTEPS; t++) {
        float xv = g_xT[t * NSEQ + n];
        float zi = wi[0] * xv + wh[0] * hv + bb[0];
        float zf = wi[1] * xv + wh[1] * hv + bb[1];
        float zg = wi[2] * xv + wh[2] * hv + bb[2];
        float zo = wi[3] * xv + wh[3] * hv + bb[3];
        cv = sigf(zf) * cv + sigf(zi) * tanhf(zg);
        hv = sigf(zo) * tanhf(cv);
        vp[t] = hv;
    }
}

// ---------------- q/k LSTM via mma.sync (HMMA) ----------------
// CTA = (hq, 32-seq tile), 512 threads = 16 warps. Balanced warp tile M=32,N=32:
// each warp computes BOTH 16-row bands for its 8 units (32 cols = 16 if + 16 go).
// B read once per step (128 KB) + A read 16x (128 KB) = 256 KB crossbar/step,
// matching the 2048-cyc HMMA floor. No B register caching (fits 128-reg cap).
// A tile (h fp16) double-buffered; one __syncthreads per step. c fp32 in regs.
#define SM_B    0          // 131072 B
#define SM_A    131072     // 16384 B  h fp16, 2 bufs x [32 rows x 256B]
#define SM_BIAS 147456     // 2048 B
#define SM_WIH  149504     // 2048 B
#define SM_TOT  151552

__global__ __launch_bounds__(512, 1) void k_qk_mma() {
    extern __shared__ char smem[];
    const int hq  = blockIdx.y;
    const int n0  = blockIdx.x * 32;
    const int tid = threadIdx.x;
    const int cg  = tid >> 5, lane = tid & 31;   // warp = col group (8 units)

    uint32_t smB = (uint32_t)__cvta_generic_to_shared(smem);
    uint32_t smA = smB + SM_A;
    float* biassm = (float*)(smem + SM_BIAS);
    float* wihsm  = (float*)(smem + SM_WIH);

    // stage B / bias / wih
    {
        const char* wsrc = (const char*)g_Wh16 + (size_t)hq * 131072;
        for (int i = tid; i < 8192; i += 512) cpa16(smem + SM_B + i * 16, wsrc + i * 16);
        if (tid < 128)
            cpa16(smem + SM_BIAS + tid * 16, (const char*)(g_bias2 + hq * 512) + tid * 16);
        else if (tid < 256)
            cpa16(smem + SM_WIH + (tid - 128) * 16,
                  (const char*)(g_wih2 + hq * 512) + (tid - 128) * 16);
        asm volatile("cp.async.commit_group;");
    }
    for (int i = tid; i < 2048; i += 512) ((uint32_t*)(smem + SM_A))[i] = 0u;  // h0=0 buf0
    asm volatile("cp.async.wait_group 0;");
    __syncthreads();

    // preload bias/wih: units u[nt] = cg*8 + nt*4 + (lane&3)
    float bi_r[2][4], wi_r[2][4];
#pragma unroll
    for (int nt = 0; nt < 2; nt++) {
        int u = cg * 8 + nt * 4 + (lane & 3);
        bi_r[nt][0] = biassm[2 * u];
        bi_r[nt][1] = biassm[2 * u + 1];
        bi_r[nt][2] = biassm[256 + 2 * u];
        bi_r[nt][3] = biassm[257 + 2 * u];
        wi_r[nt][0] = wihsm[2 * u];
        wi_r[nt][1] = wihsm[2 * u + 1];
        wi_r[nt][2] = wihsm[256 + 2 * u];
        wi_r[nt][3] = wihsm[257 + 2 * u];
    }

    float cst[2][2][2];   // [band][nt][hi]
#pragma unroll
    for (int b = 0; b < 2; b++)
#pragma unroll
        for (int nt = 0; nt < 2; nt++) {
            cst[b][nt][0] = 0.f;
            cst[b][nt][1] = 0.f;
        }

    // ldmatrix lane geometry
    const int arow = (lane & 7) + ((lane >> 3) & 1) * 8;   // band-0 row
    const uint32_t a_off0 = arow * 256;
    const uint32_t a_off1 = (arow + 16) * 256;
    const uint32_t a_xr = (arow & 7) << 4;
    const uint32_t a_kd = (lane >> 4) * 16;

    const int dlB = (lane & 7) + (lane >> 4) * 8;          // 0..15 within 16-col group
    const uint32_t b_kd = ((lane >> 3) & 1) * 16;
    const uint32_t b_xr = (dlB & 7) << 4;
    const uint32_t bif = smB + (cg * 16 + dlB) * 256;      // if-cols (n = cg*16 + dlB)
    const uint32_t bgo = bif + 65536;                      // go-cols (n + 256)

    const int r00 = lane >> 2;   // band0 lo row
    const float* xp0 = g_xT + n0 + r00;        // rows r00, +8, +16, +24

    for (int t = 0; t < LSTEPS; t++) {
        const uint32_t rbuf = smA + ((t & 1) ? 8192u : 0u);
        const uint32_t wbuf = smA + ((t & 1) ? 0u : 8192u);

        // per-thread x loads (4 rows)
        float xv[2][2];
        xv[0][0] = xp0[t * NSEQ];
        xv[0][1] = xp0[t * NSEQ + 8];
        xv[1][0] = xp0[t * NSEQ + 16];
        xv[1][1] = xp0[t * NSEQ + 24];

        float accif[2][8], accgo[2][8];
#pragma unroll
        for (int b = 0; b < 2; b++)
#pragma unroll
            for (int i = 0; i < 8; i++) { accif[b][i] = 0.f; accgo[b][i] = 0.f; }

#pragma unroll
        for (int ks = 0; ks < 8; ks++) {
            uint32_t a0[4], a1[4], b0[4], b1[4];
            uint32_t ako = ((uint32_t)(ks * 32) + a_kd) ^ a_xr;
            uint32_t ko  = ((uint32_t)(ks * 32) + b_kd) ^ b_xr;
            ldsm4(a0, rbuf + a_off0 + ako);
            ldsm4(a1, rbuf + a_off1 + ako);
            ldsm4(b0, bif + ko);            // if-cols: nt0, nt1
            ldsm4(b1, bgo + ko);            // go-cols: nt0, nt1

            mma16816(accif[0] + 0, a0, b0 + 0);
            mma16816(accif[0] + 4, a0, b0 + 2);
            mma16816(accif[1] + 0, a1, b0 + 0);
            mma16816(accif[1] + 4, a1, b0 + 2);
            mma16816(accgo[0] + 0, a0, b1 + 0);
            mma16816(accgo[0] + 4, a0, b1 + 2);
            mma16816(accgo[1] + 0, a1, b1 + 0);
            mma16816(accgo[1] + 4, a1, b1 + 2);
        }

        const bool last = (t == LSTEPS - 1);

#pragma unroll
        for (int b = 0; b < 2; b++) {
#pragma unroll
            for (int nt = 0; nt < 2; nt++) {
#pragma unroll
                for (int hi = 0; hi < 2; hi++) {
                    float xvv = xv[b][hi];
                    int   row = b * 16 + r00 + hi * 8;
                    float zi = accif[b][nt * 4 + hi * 2]     + bi_r[nt][0] + wi_r[nt][0] * xvv;
                    float zf = accif[b][nt * 4 + hi * 2 + 1] + bi_r[nt][1] + wi_r[nt][1] * xvv;
                    float zg = accgo[b][nt * 4 + hi * 2]     + bi_r[nt][2] + wi_r[nt][2] * xvv;
                    float zo = accgo[b][nt * 4 + hi * 2 + 1] + bi_r[nt][3] + wi_r[nt][3] * xvv;
                    float cp = cst[b][nt][hi];
                    float cn = siga(zf) * cp + siga(zi) * tanha(zg);
                    float hn = siga(zo) * tanha(cn);
                    cst[b][nt][hi] = cn;
                    int u = cg * 8 + nt * 4 + (lane & 3);
                    if (!last) {
                        uint32_t addr = wbuf + row * 256 +
                                        (((uint32_t)(2 * u)) ^ ((row & 7) << 4));
                        __half hh = __float2half(hn);
                        asm volatile("st.shared.b16 [%0], %1;"
                                     :: "r"(addr), "h"(*(unsigned short*)&hh));
                    } else {
                        int ng = n0 + row;
                        if (hq < 8) g_q[((size_t)hq * NSEQ + ng) * HID + u] = hn;
                        else        g_kT[((size_t)(hq - 8) * HID + u) * NSEQ + ng] = hn;
                    }
                }
            }
        }
        __syncthreads();   // h(t+1) stores visible to all 16 warps
    }
}

// ---------------- fused attention: scores + leaky + mask + softmax + attn@v + leaky ----------------
__global__ void k_attn(const float* __restrict__ graph, float* __restrict__ out) {
    int h = blockIdx.z, b = blockIdx.y, s0 = blockIdx.x * 16;
    int tid = threadIdx.x;
    __shared__ float qs[16][HID];
    __shared__ float sc[16][328];

    for (int i = tid; i < 16 * HID; i += 256) {
        int sq = i >> 7, d = i & 127;
        int s = s0 + sq;
        qs[sq][d] = (s < SLEN) ? g_q[((size_t)h * NSEQ + b * SLEN + s) * HID + d] : 0.f;
    }
    __syncthreads();

    for (int t = tid; t < SLEN; t += 256) {
        float acc[16];
#pragma unroll
        for (int i = 0; i < 16; i++) acc[i] = 0.f;
        const float* kp = g_kT + (size_t)h * HID * NSEQ + b * SLEN + t;
        for (int d = 0; d < HID; d += 4) {
            float k0 = kp[(size_t)d * NSEQ];
            float k1 = kp[(size_t)(d + 1) * NSEQ];
            float k2 = kp[(size_t)(d + 2) * NSEQ];
            float k3 = kp[(size_t)(d + 3) * NSEQ];
#pragma unroll
            for (int sq = 0; sq < 16; sq++) {
                float4 q4 = *reinterpret_cast<const float4*>(&qs[sq][d]);
                acc[sq] += k0 * q4.x + k1 * q4.y + k2 * q4.z + k3 * q4.w;
            }
        }
#pragma unroll
        for (int sq = 0; sq < 16; sq++) {
            int s = s0 + sq;
            float v = acc[sq] * SCALE;
            v = v >= 0.f ? v : 0.2f * v;
            bool keep = (s < SLEN) && ((s == t) || (graph[t * SLEN + s] != 0.f));
            sc[sq][t] = keep ? v : -1e9f;
        }
    }
    __syncthreads();

    {
        int r = tid >> 4, ln = tid & 15;
        float mx = -3.4e38f;
        for (int i = ln; i < SLEN; i += 16) mx = fmaxf(mx, sc[r][i]);
#pragma unroll
        for (int o = 1; o < 16; o <<= 1) mx = fmaxf(mx, __shfl_xor_sync(0xffffffffu, mx, o));
        float sum = 0.f;
        for (int i = ln; i < SLEN; i += 16) {
            float e = __expf(sc[r][i] - mx);
            sc[r][i] = e;
            sum += e;
        }
#pragma unroll
        for (int o = 1; o < 16; o <<= 1) sum += __shfl_xor_sync(0xffffffffu, sum, o);
        float inv = 1.f / sum;
        for (int i = ln; i < SLEN; i += 16) sc[r][i] *= inv;
    }
    __syncthreads();

    {
        int lg = tid & 63, sg = tid >> 6;
        float a2[4][3];
#pragma unroll
        for (int ss = 0; ss < 4; ss++) { a2[ss][0] = 0.f; a2[ss][1] = 0.f; a2[ss][2] = 0.f; }
        const float* vb = g_v + ((size_t)h * NSEQ + b * SLEN) * LSTEPS;
        for (int t = 0; t < SLEN; t++) {
            float a[4];
#pragma unroll
            for (int ss = 0; ss < 4; ss++) a[ss] = sc[sg * 4 + ss][t];
            const float* vr = vb + (size_t)t * LSTEPS + lg * 3;
            float v0 = vr[0], v1 = vr[1], v2 = vr[2];
#pragma unroll
            for (int ss = 0; ss < 4; ss++) {
                a2[ss][0] += a[ss] * v0;
                a2[ss][1] += a[ss] * v1;
                a2[ss][2] += a[ss] * v2;
            }
        }
#pragma unroll
        for (int ss = 0; ss < 4; ss++) {
            int s = s0 + sg * 4 + ss;
            if (s < SLEN) {
#pragma unroll
                for (int q = 0; q < 3; q++) {
                    float vv = a2[ss][q];
                    vv = vv >= 0.f ? vv : 0.2f * vv;
                    int l = lg * 3 + q;
                    out[(((size_t)(b * SLEN + s)) * LSTEPS + l) * NH + h] = vv;
                }
            }
        }
    }
}

// ---------------- launch ----------------
extern "C" void kernel_launch(void* const* d_in, const int* in_sizes, int n_in,
                              void* d_out, int out_size) {
    const float* x     = (const float*)d_in[0];
    const float* graph = (const float*)d_in[1];
    const float* qWih  = (const float*)d_in[2];
    const float* qWhh  = (const float*)d_in[3];
    const float* qbih  = (const float*)d_in[4];
    const float* qbhh  = (const float*)d_in[5];
    const float* kWih  = (const float*)d_in[6];
    const float* kWhh  = (const float*)d_in[7];
    const float* kbih  = (const float*)d_in[8];
    const float* kbhh  = (const float*)d_in[9];
    const float* vWih  = (const float*)d_in[10];
    const float* vWhh  = (const float*)d_in[11];
    const float* vbih  = (const float*)d_in[12];
    const float* vbhh  = (const float*)d_in[13];
    float* out = (float*)d_out;

    cudaFuncSetAttribute(k_qk_mma, cudaFuncAttributeMaxDynamicSharedMemorySize, SM_TOT);

    k_prep_x<<<(LSTEPS * NSEQ + 255) / 256, 256>>>(x);
    k_prep_w16<<<(16 * 512 * HID + 255) / 256, 256>>>(qWih, qWhh, qbih, qbhh,
                                                      kWih, kWhh, kbih, kbhh);
    k_v_lstm<<<(NH * NSEQ + 255) / 256, 256>>>(vWih, vWhh, vbih, vbhh);
    k_qk_mma<<<dim3(325, 16, 1), 512, SM_TOT>>>();
    k_attn<<<dim3(21, NB, NH), 256>>>(graph, out);
}